// round 11
// baseline (speedup 1.0000x reference)
#include <cuda_runtime.h>

// SPU transformer bound propagation — pure elementwise over N=8388608. FINAL.
//
// Roofline verdict (10 rounds of evidence):
//   traffic  : 4x64MiB in + 64MiB out = 320 MiB  (information floor — all
//              five streams are required, fp32 is the contract dtype)
//   achieved : 6.5-6.7 TB/s sustained = B300 LTS chip cap (~6300 B/cyc,
//              path-independent; TMA would see the same ceiling)
//   kernel   : 45.6-47.0 us; bench 51.2-51.7 (residual = harness + DVFS noise)
//
// Converged optimum: flat launch, 256 thr/blk, one float4 per array per
// thread (4x independent LDG.128 + 1x STG.128), __ldcs/__stcs evict-first
// (zero-reuse stream), __fdividef fast-rcp divisions, 31 regs, occ ~84%.
//
// Tried and rejected with measurements:
//   unroll x4 front-batched loads : 80 regs, occ 34%, DRAM 78%  -> REGRESSED
//   persistent single-wave loop   : 44 regs, occ 49%, DRAM 72%  -> REGRESSED
//   block sizes 128 / 512         : within +-1% of 256          -> NEUTRAL
//   __fdividef                    : fma 21->16%, issue 47->38%  -> NEUTRAL
//                                   (DRAM-bound; kept for the reg/instr slack)

__device__ __forceinline__ float spu_f(float x) {
    // x>=0: x*x - 0.5 ; x<0: sigmoid(-x) - 1 = -e^x / (1 + e^x)
    float ex = __expf(x);
    float negv = -__fdividef(ex, 1.0f + ex);
    float posv = fmaf(x, x, -0.5f);
    return x >= 0.0f ? posv : negv;
}

__device__ __forceinline__ void spu_elem(
    float l, float u,          // bounds
    float p1l, float p1u,      // slopes_prev
    float q1l, float q1u,      // shifts_prev
    float b0l, float b0u,      // bounds_prev
    float& out_lo, float& out_hi)
{
    float sl = spu_f(l);
    float su = spu_f(u);

    bool neg   = (u <= 0.0f);
    bool pos   = (l >= 0.0f);
    bool cross = !(neg || pos);

    float slope = __fdividef(su - sl, u - l);   // u-l >= 0.02, safe

    float s0 = neg ? slope : 0.0f;
    float s1 = neg ? 0.0f  : slope;     // pos|cross == !neg

    bool neg_slope = (slope < 0.0f);
    float lo = neg_slope ? su : sl;
    float hi = neg_slope ? sl : su;
    lo = cross ? -0.5f : lo;

    float sh1 = fmaf(-s1, u, su);
    float sh0 = fmaf(-s0, l, sl);
    sh0 = cross ? -0.5f : sh0;
    sh1 = neg   ? sl    : sh1;

    float s1p = fmaxf(s1, 0.0f), s1n = fminf(s1, 0.0f);
    float s0p = fmaxf(s0, 0.0f), s0n = fminf(s0, 0.0f);

    float UBM = fmaf(s1p, p1u, s1n * p1l);
    float UBV = fmaf(s1p, q1u, fmaf(s1n, q1l, sh1));
    float LBM = fmaf(s0p, p1l, s0n * p1u);
    float LBV = fmaf(s0n, q1l, fmaf(s0p, q1u, sh0));

    float lower = fmaf(fmaxf(LBM, 0.0f), b0l, fmaf(fminf(LBM, 0.0f), b0u, LBV));
    float upper = fmaf(fmaxf(UBM, 0.0f), b0u, fmaf(fminf(UBM, 0.0f), b0l, UBV));

    out_lo = (lower > lo) ? lower : lo;
    out_hi = (upper < hi) ? upper : hi;
}

__global__ void __launch_bounds__(256)
spu_kernel(const float4* __restrict__ bounds,
           const float4* __restrict__ slopes_prev,
           const float4* __restrict__ shifts_prev,
           const float4* __restrict__ bounds_prev,
           float4* __restrict__ out,
           int n_vec)   // n_vec = N/2 float4s, each covering 2 elements
{
    int i = blockIdx.x * blockDim.x + threadIdx.x;
    if (i >= n_vec) return;

    float4 b  = __ldcs(&bounds[i]);
    float4 sp = __ldcs(&slopes_prev[i]);
    float4 sh = __ldcs(&shifts_prev[i]);
    float4 bp = __ldcs(&bounds_prev[i]);

    float4 r;
    spu_elem(b.x, b.y, sp.x, sp.y, sh.x, sh.y, bp.x, bp.y, r.x, r.y);
    spu_elem(b.z, b.w, sp.z, sp.w, sh.z, sh.w, bp.z, bp.w, r.z, r.w);

    __stcs(&out[i], r);
}

extern "C" void kernel_launch(void* const* d_in, const int* in_sizes, int n_in,
                              void* d_out, int out_size) {
    // metadata order: bounds (N,2), slopes_prev (N,2), shifts_prev (N,2), bounds_prev (N,2)
    const float4* bounds      = (const float4*)d_in[0];
    const float4* slopes_prev = (const float4*)d_in[1];
    const float4* shifts_prev = (const float4*)d_in[2];
    const float4* bounds_prev = (const float4*)d_in[3];
    float4* out = (float4*)d_out;

    int n_floats = in_sizes[0];          // N*2
    int n_vec = n_floats / 4;            // float4 count (N*2 divisible by 4)

    int threads = 256;
    int blocks = (n_vec + threads - 1) / threads;
    spu_kernel<<<blocks, threads>>>(bounds, slopes_prev, shifts_prev, bounds_prev, out, n_vec);
}

// round 12
// speedup vs baseline: 1.0137x; 1.0137x over previous
#include <cuda_runtime.h>

// SPU transformer bound propagation — pure elementwise over N=8388608. FINAL.
//
// Roofline verdict (11 rounds of evidence):
//   traffic  : 4x64MiB in + 64MiB out = 320 MiB (information floor — all five
//              streams required, fp32 contract dtype)
//   achieved : 6.5-6.7 TB/s sustained = B300 LTS chip cap (~6300 B/cyc,
//              path-independent; TMA would hit the same ceiling)
//   kernel   : 45.6-47.2 us; bench 51.2-51.9 (residual = harness + DVFS noise)
//
// This source is the best-measured configuration (R3/R8): flat launch,
// 256 thr/blk, one float4 per array per thread (4x independent LDG.128 +
// STG.128), __ldcs/__stcs evict-first (zero-reuse stream), plain IEEE
// division (pure-FFMA Newton sequence pipelines better in the load shadow
// than MUFU.RCP), 32 regs, occ ~84%, DRAM 84-85%.
//
// Tried and rejected with measurements:
//   unroll x4 front-batched loads : 80 regs, occ 34%, DRAM 78% -> REGRESSED
//   persistent single-wave loop   : 44 regs, occ 49%, DRAM 72% -> REGRESSED
//   block sizes 128 / 512         : within +-1% of 256         -> NEUTRAL
//   __fdividef                    : no wallclock gain; slight DRAM% dip -> reverted

__device__ __forceinline__ float spu_f(float x) {
    // x>=0: x*x - 0.5 ; x<0: sigmoid(-x) - 1 = -e^x / (1 + e^x)
    float ex = __expf(x);
    float negv = -ex / (1.0f + ex);
    float posv = fmaf(x, x, -0.5f);
    return x >= 0.0f ? posv : negv;
}

__device__ __forceinline__ void spu_elem(
    float l, float u,          // bounds
    float p1l, float p1u,      // slopes_prev
    float q1l, float q1u,      // shifts_prev
    float b0l, float b0u,      // bounds_prev
    float& out_lo, float& out_hi)
{
    float sl = spu_f(l);
    float su = spu_f(u);

    bool neg   = (u <= 0.0f);
    bool pos   = (l >= 0.0f);
    bool cross = !(neg || pos);

    float slope = (su - sl) / (u - l);   // u-l >= 0.02, safe

    float s0 = neg ? slope : 0.0f;
    float s1 = neg ? 0.0f  : slope;     // pos|cross == !neg

    bool neg_slope = (slope < 0.0f);
    float lo = neg_slope ? su : sl;
    float hi = neg_slope ? sl : su;
    lo = cross ? -0.5f : lo;

    float sh1 = fmaf(-s1, u, su);
    float sh0 = fmaf(-s0, l, sl);
    sh0 = cross ? -0.5f : sh0;
    sh1 = neg   ? sl    : sh1;

    float s1p = fmaxf(s1, 0.0f), s1n = fminf(s1, 0.0f);
    float s0p = fmaxf(s0, 0.0f), s0n = fminf(s0, 0.0f);

    float UBM = fmaf(s1p, p1u, s1n * p1l);
    float UBV = fmaf(s1p, q1u, fmaf(s1n, q1l, sh1));
    float LBM = fmaf(s0p, p1l, s0n * p1u);
    float LBV = fmaf(s0n, q1l, fmaf(s0p, q1u, sh0));

    float lower = fmaf(fmaxf(LBM, 0.0f), b0l, fmaf(fminf(LBM, 0.0f), b0u, LBV));
    float upper = fmaf(fmaxf(UBM, 0.0f), b0u, fmaf(fminf(UBM, 0.0f), b0l, UBV));

    out_lo = (lower > lo) ? lower : lo;
    out_hi = (upper < hi) ? upper : hi;
}

__global__ void __launch_bounds__(256)
spu_kernel(const float4* __restrict__ bounds,
           const float4* __restrict__ slopes_prev,
           const float4* __restrict__ shifts_prev,
           const float4* __restrict__ bounds_prev,
           float4* __restrict__ out,
           int n_vec)   // n_vec = N/2 float4s, each covering 2 elements
{
    int i = blockIdx.x * blockDim.x + threadIdx.x;
    if (i >= n_vec) return;

    float4 b  = __ldcs(&bounds[i]);
    float4 sp = __ldcs(&slopes_prev[i]);
    float4 sh = __ldcs(&shifts_prev[i]);
    float4 bp = __ldcs(&bounds_prev[i]);

    float4 r;
    spu_elem(b.x, b.y, sp.x, sp.y, sh.x, sh.y, bp.x, bp.y, r.x, r.y);
    spu_elem(b.z, b.w, sp.z, sp.w, sh.z, sh.w, bp.z, bp.w, r.z, r.w);

    __stcs(&out[i], r);
}

extern "C" void kernel_launch(void* const* d_in, const int* in_sizes, int n_in,
                              void* d_out, int out_size) {
    // metadata order: bounds (N,2), slopes_prev (N,2), shifts_prev (N,2), bounds_prev (N,2)
    const float4* bounds      = (const float4*)d_in[0];
    const float4* slopes_prev = (const float4*)d_in[1];
    const float4* shifts_prev = (const float4*)d_in[2];
    const float4* bounds_prev = (const float4*)d_in[3];
    float4* out = (float4*)d_out;

    int n_floats = in_sizes[0];          // N*2
    int n_vec = n_floats / 4;            // float4 count (N*2 divisible by 4)

    int threads = 256;
    int blocks = (n_vec + threads - 1) / threads;
    spu_kernel<<<blocks, threads>>>(bounds, slopes_prev, shifts_prev, bounds_prev, out, n_vec);
}